// round 8
// baseline (speedup 1.0000x reference)
#include <cuda_runtime.h>
#include <stdint.h>

// Fixed problem shape: features [8192, 512], labels [8192] in [0,64)
#define NB 8192
#define ND 512
#define NNEG 8
#define HALFC 33554432u        // (8192*8192)/2
#define THRESH_RAW 0xFC000000u // raw-bits threshold == (2^23 * (1-1/64)) << 9
#define NCAP 512               // survivor cap per row (mean 126; P(>512) ~ 0)
#define NSLOT (NCAP / 32)
#define CLS 320                // class-list cap (mean 128; P(>320) ~ 0)

// Scratch (no cudaMalloc allowed)
__device__ float g_loss[NB];

// ---------------- rotate: single SHF on device, portable on host -------------
__host__ __device__ __forceinline__ uint32_t rotl32(uint32_t v, int r)
{
#ifdef __CUDA_ARCH__
    return __funnelshift_l(v, v, r);     // guaranteed 1x SHF
#else
    return (v << r) | (v >> (32 - r));
#endif
}

// ---------------- Threefry-2x32 (20 rounds), original JAX convention ----------
__host__ __device__ __forceinline__ void threefry2x32(
    uint32_t k0, uint32_t k1, uint32_t x0, uint32_t x1,
    uint32_t* o0, uint32_t* o1)
{
    uint32_t ks2 = k0 ^ k1 ^ 0x1BD11BDAu;
    x0 += k0; x1 += k1;
#define TF_RND(r) { x0 += x1; x1 = rotl32(x1, r); x1 ^= x0; }
    TF_RND(13) TF_RND(15) TF_RND(26) TF_RND(6)  x0 += k1;  x1 += ks2 + 1u;
    TF_RND(17) TF_RND(29) TF_RND(16) TF_RND(24) x0 += ks2; x1 += k0  + 2u;
    TF_RND(13) TF_RND(15) TF_RND(26) TF_RND(6)  x0 += k0;  x1 += k1  + 3u;
    TF_RND(17) TF_RND(29) TF_RND(16) TF_RND(24) x0 += k1;  x1 += ks2 + 4u;
    TF_RND(13) TF_RND(15) TF_RND(26) TF_RND(6)  x0 += ks2; x1 += k0  + 5u;
#undef TF_RND
    *o0 = x0; *o1 = x1;
}

// ordering of gumbel == ordering of (bits>>9); tie -> lower j wins.
__device__ __forceinline__ unsigned long long pack_key(uint32_t bits, int j)
{
    return ((unsigned long long)(bits >> 9) << 13) |
           (unsigned long long)(NB - 1 - j);
}

__device__ __forceinline__ unsigned long long warp_max_u64(unsigned long long v)
{
    #pragma unroll
    for (int o = 16; o; o >>= 1) {
        unsigned long long u = __shfl_xor_sync(0xffffffffu, v, o);
        if (u > v) v = u;
    }
    return v;
}

// ---------------- Kernel 1: row-PAIR selection + fused loss (self-contained) --
// Block b handles rows i_lo=b, i_hi=b+NB/2 (counter pair shares one threefry:
// o0 -> row lo, o1 -> row hi). Selection identical to R4/R7 (threshold + exact
// top-8). Labels packed from the i64 input at block start (L1-resident).
// Tail: 18 dots on raw features; partner & anchor sum-of-squares computed
// inline with the SAME lane+32k summation pattern as the old k_norms, so inv
// values are bit-identical. No k_norms kernel, no g_inv/g_lab globals.
__global__ __launch_bounds__(256) void k_select_loss(
    const float* __restrict__ feat,
    const long long* __restrict__ labels,
    uint32_t kp0, uint32_t kp1, uint32_t kn0, uint32_t kn1)
{
    const int i_lo = blockIdx.x;           // 0..4095
    const int i_hi = i_lo + (NB >> 1);
    const int tid = threadIdx.x, lane = tid & 31, wid = tid >> 5;

    __shared__ uint4 slab4[NB / 16];                      // labels, 8 KB
    __shared__ unsigned long long nsurv[2][NCAP];         // 8 KB
    __shared__ int ncnt[2];
    __shared__ short clist[2][CLS];                       // 1.25 KB
    __shared__ int ccnt[2];
    __shared__ unsigned long long spos[2][8];
    __shared__ int    sidx[2][1 + NNEG];                  // partner indices
    __shared__ float4 srow4[2][ND / 4];                   // anchor rows (4 KB)
    __shared__ float  sdots[2][1 + NNEG];                 // raw dots
    __shared__ float  ssqp[2][1 + NNEG];                  // partner sum-of-squares
    __shared__ float  sanc[2];                            // anchor sum-of-squares

    const unsigned char* slab = (const unsigned char*)slab4;

    // pack labels (int64 low byte) into smem: 2 labels per ulonglong2 load
    {
        const ulonglong2* lab2 = (const ulonglong2*)labels;
        unsigned short* s16 = (unsigned short*)slab4;
        for (int c = tid; c < NB / 2; c += 256) {
            ulonglong2 v = lab2[c];
            s16[c] = (unsigned short)(((unsigned)v.x & 0xFFu) |
                                      (((unsigned)v.y & 0xFFu) << 8));
        }
    }
    if (tid < 2) { ncnt[tid] = 0; ccnt[tid] = 0; }
    __syncthreads();

    const unsigned int lab_lo = slab[i_lo];
    const unsigned int lab_hi = slab[i_hi];
    const uint32_t lablo4 = lab_lo * 0x01010101u;
    const uint32_t labhi4 = lab_hi * 0x01010101u;
    const uint32_t nbase = (uint32_t)i_lo * (uint32_t)NB;

    // ---- hot loop: 8192 threefry blocks, threshold filter ----
    for (int jb = tid * 4; jb < NB; jb += 1024) {
        uint32_t lw = ((const uint32_t*)slab)[jb >> 2];
        uint32_t eqlo = __vcmpeq4(lw, lablo4);            // 0xFF per match byte
        uint32_t eqhi = __vcmpeq4(lw, labhi4);
        #pragma unroll
        for (int q = 0; q < 4; q++) {
            int j = jb + q;
            uint32_t n = nbase + (uint32_t)j;
            uint32_t o0, o1;
            threefry2x32(kn0, kn1, n, n + HALFC, &o0, &o1);

            if (eqlo & (0xFFu << (8 * q))) {
                int p = atomicAdd(&ccnt[0], 1);
                if (p < CLS) clist[0][p] = (short)j;
            } else if (o0 >= THRESH_RAW) {
                int p = atomicAdd(&ncnt[0], 1);
                if (p < NCAP) nsurv[0][p] = pack_key(o0, j);
            }
            if (eqhi & (0xFFu << (8 * q))) {
                int p = atomicAdd(&ccnt[1], 1);
                if (p < CLS) clist[1][p] = (short)j;
            } else if (o1 >= THRESH_RAW) {
                int p = atomicAdd(&ncnt[1], 1);
                if (p < NCAP) nsurv[1][p] = pack_key(o1, j);
            }
        }
    }
    __syncthreads();

    // ---- sparse positive loops (kp key) ----
    unsigned long long bp_lo = 0ull, bp_hi = 0ull;
    {
        int c0 = min(ccnt[0], CLS);
        for (int t = tid; t < c0; t += 256) {
            int j = clist[0][t];
            if (j != i_lo) {
                uint32_t n = nbase + (uint32_t)j, o0, o1;
                threefry2x32(kp0, kp1, n, n + HALFC, &o0, &o1);
                unsigned long long p = pack_key(o0, j);
                if (p > bp_lo) bp_lo = p;
            }
        }
        int c1 = min(ccnt[1], CLS);
        for (int t = tid; t < c1; t += 256) {
            int j = clist[1][t];
            if (j != i_hi) {
                uint32_t n = nbase + (uint32_t)j, o0, o1;
                threefry2x32(kp0, kp1, n, n + HALFC, &o0, &o1);
                unsigned long long p = pack_key(o1, j);
                if (p > bp_hi) bp_hi = p;
            }
        }
    }
    bp_lo = warp_max_u64(bp_lo);
    bp_hi = warp_max_u64(bp_hi);
    if (lane == 0) { spos[0][wid] = bp_lo; spos[1][wid] = bp_hi; }
    __syncthreads();

    // ---- parallel tail: warps 0-1 extract top-8 + pos; warps 2-7 preload rows
    if (wid < 2) {
        const int row = wid;
        int cnt = min(ncnt[row], NCAP);
        unsigned long long v[NSLOT];
        #pragma unroll
        for (int s = 0; s < NSLOT; s++) {
            int idx = lane + 32 * s;
            v[s] = (idx < cnt) ? nsurv[row][idx] : 0ull;
        }
        #pragma unroll
        for (int r = 0; r < NNEG; r++) {
            unsigned long long loc = 0ull;
            #pragma unroll
            for (int s = 0; s < NSLOT; s++) if (v[s] > loc) loc = v[s];
            unsigned long long g = warp_max_u64(loc);
            #pragma unroll
            for (int s = 0; s < NSLOT; s++) if (v[s] == g) v[s] = 0ull;  // unique pop
            if (lane == 0) sidx[row][1 + r] = NB - 1 - (int)(g & 0x1FFFull);
        }
        unsigned long long bp = (lane < 8) ? spos[row][lane] : 0ull;
        bp = warp_max_u64(bp);
        if (lane == 0)
            sidx[row][0] = (bp == 0ull) ? 0 : (NB - 1 - (int)(bp & 0x1FFFull));
    } else {
        // load anchor rows i_lo, i_hi (raw) into smem: 256 float4 by 192 threads
        int idx = tid - 64;
        for (int c = idx; c < 2 * (ND / 4); c += 192) {
            int row = c >> 7;                 // 128 float4 per row
            int col = c & 127;
            const int i_row = row ? i_hi : i_lo;
            srow4[row][col] =
                ((const float4*)(feat + (size_t)i_row * ND))[col];
        }
    }
    __syncthreads();

    // ---- tasks: 0..17 = dots (+ partner ssq); 18,19 = anchor ssq ----
    for (int t = wid; t < 20; t += 8) {
        if (t < 18) {
            int row  = t / (1 + NNEG);
            int slot = t % (1 + NNEG);
            int j = sidx[row][slot];
            const float4* fr = (const float4*)(feat + (size_t)j * ND);
            const float4* ar = srow4[row];
            float acc = 0.0f, sq = 0.0f;
            #pragma unroll
            for (int k = 0; k < 4; k++) {
                float4 a = ar[lane + 32 * k];
                float4 b = fr[lane + 32 * k];
                acc += a.x * b.x + a.y * b.y + a.z * b.z + a.w * b.w;
                sq  += b.x * b.x + b.y * b.y + b.z * b.z + b.w * b.w;
            }
            #pragma unroll
            for (int o = 16; o; o >>= 1) {
                acc += __shfl_xor_sync(0xffffffffu, acc, o);
                sq  += __shfl_xor_sync(0xffffffffu, sq,  o);
            }
            if (lane == 0) { sdots[row][slot] = acc; ssqp[row][slot] = sq; }
        } else {
            int row = t - 18;
            const float4* ar = srow4[row];
            float sq = 0.0f;
            #pragma unroll
            for (int k = 0; k < 4; k++) {
                float4 a = ar[lane + 32 * k];
                sq += a.x * a.x + a.y * a.y + a.z * a.z + a.w * a.w;
            }
            #pragma unroll
            for (int o = 16; o; o >>= 1) sq += __shfl_xor_sync(0xffffffffu, sq, o);
            if (lane == 0) sanc[row] = sq;
        }
    }
    __syncthreads();

    // ---- loss epilogue: thread 0 -> row lo, thread 1 -> row hi ----
    if (tid < 2) {
        const int row = tid;
        const int i_row = row ? i_hi : i_lo;
        float inv_i = 1.0f / fmaxf(sqrtf(sanc[row]), 1e-12f);
        float sims[1 + NNEG];
        #pragma unroll
        for (int q = 0; q < 1 + NNEG; q++) {
            float inv_j = 1.0f / fmaxf(sqrtf(ssqp[row][q]), 1e-12f);
            sims[q] = sdots[row][q] * inv_i * inv_j;
        }
        float pos = sims[0] * 2.0f;          // / TEMPERATURE (0.5)
        float s[NNEG];
        #pragma unroll
        for (int q = 0; q < NNEG; q++) s[q] = sims[1 + q];
        float hard[3];
        #pragma unroll
        for (int r = 0; r < 3; r++) {        // stable top-3 (lower index wins)
            int bi = 0; float bv = s[0];
            #pragma unroll
            for (int q = 1; q < NNEG; q++) if (s[q] > bv) { bv = s[q]; bi = q; }
            hard[r] = bv * 2.0f;
            s[bi] = -3.0e38f;
        }
        float mx = fmaxf(fmaxf(pos, hard[0]), fmaxf(hard[1], hard[2]));
        float sum = expf(pos - mx) + expf(hard[0] - mx) +
                    expf(hard[1] - mx) + expf(hard[2] - mx);
        g_loss[i_row] = mx + logf(sum) - pos;
    }
}

// ---------------- Kernel 2: mean reduce ----------------
__global__ void k_reduce(float* __restrict__ out)
{
    __shared__ float s[256];
    int tid = threadIdx.x;
    float a = 0.0f;
    for (int i = tid; i < NB; i += 256) a += g_loss[i];
    s[tid] = a;
    __syncthreads();
    for (int off = 128; off; off >>= 1) {
        if (tid < off) s[tid] += s[tid + off];
        __syncthreads();
    }
    if (tid == 0) out[0] = s[0] / (float)NB;
}

// ---------------- Launch ----------------
extern "C" void kernel_launch(void* const* d_in, const int* in_sizes, int n_in,
                              void* d_out, int out_size)
{
    const float*     feat   = (const float*)d_in[0];
    const long long* labels = (const long long*)d_in[1];

    // seed 42 -> raw key (0, 42); original split: counts iota(4) -> pairs
    // (0,2),(1,3); kp=(a0,a1), kn=(b0,b1)
    uint32_t a0, b0, a1, b1;
    threefry2x32(0u, 42u, 0u, 2u, &a0, &b0);
    threefry2x32(0u, 42u, 1u, 3u, &a1, &b1);
    uint32_t kp0 = a0, kp1 = a1, kn0 = b0, kn1 = b1;

    k_select_loss<<<NB / 2, 256>>>(feat, labels, kp0, kp1, kn0, kn1);
    k_reduce     <<<1, 256>>>((float*)d_out);
}

// round 10
// speedup vs baseline: 1.0352x; 1.0352x over previous
#include <cuda_runtime.h>
#include <stdint.h>

// Fixed problem shape: features [8192, 512], labels [8192] in [0,64)
#define NB 8192
#define ND 512
#define NNEG 8
#define HALFC 33554432u        // (8192*8192)/2
#define THRESH_RAW 0xFC000000u // raw-bits threshold == (2^23 * (1-1/64)) << 9
#define NCAP 512               // survivor cap per row (mean 126; P(>512) ~ 0)
#define NSLOT (NCAP / 32)
#define CLS 320                // class-list cap (mean 128; P(>320) ~ 0)

// Scratch (no cudaMalloc allowed)
__device__ unsigned char g_lab[NB];
__device__ float         g_loss[NB];

// ---------------- rotate: single SHF on device, portable on host -------------
__host__ __device__ __forceinline__ uint32_t rotl32(uint32_t v, int r)
{
#ifdef __CUDA_ARCH__
    return __funnelshift_l(v, v, r);
#else
    return (v << r) | (v >> (32 - r));
#endif
}

// ---------------- Threefry-2x32 (20 rounds), original JAX convention ----------
__host__ __device__ __forceinline__ void threefry2x32(
    uint32_t k0, uint32_t k1, uint32_t x0, uint32_t x1,
    uint32_t* o0, uint32_t* o1)
{
    uint32_t ks2 = k0 ^ k1 ^ 0x1BD11BDAu;
    x0 += k0; x1 += k1;
#define TF_RND(r) { x0 += x1; x1 = rotl32(x1, r); x1 ^= x0; }
    TF_RND(13) TF_RND(15) TF_RND(26) TF_RND(6)  x0 += k1;  x1 += ks2 + 1u;
    TF_RND(17) TF_RND(29) TF_RND(16) TF_RND(24) x0 += ks2; x1 += k0  + 2u;
    TF_RND(13) TF_RND(15) TF_RND(26) TF_RND(6)  x0 += k0;  x1 += k1  + 3u;
    TF_RND(17) TF_RND(29) TF_RND(16) TF_RND(24) x0 += k1;  x1 += ks2 + 4u;
    TF_RND(13) TF_RND(15) TF_RND(26) TF_RND(6)  x0 += ks2; x1 += k0  + 5u;
#undef TF_RND
    *o0 = x0; *o1 = x1;
}

// ordering of gumbel == ordering of (bits>>9); tie -> lower j wins.
__device__ __forceinline__ unsigned long long pack_key(uint32_t bits, int j)
{
    return ((unsigned long long)(bits >> 9) << 13) |
           (unsigned long long)(NB - 1 - j);
}

__device__ __forceinline__ unsigned long long warp_max_u64(unsigned long long v)
{
    #pragma unroll
    for (int o = 16; o; o >>= 1) {
        unsigned long long u = __shfl_xor_sync(0xffffffffu, v, o);
        if (u > v) v = u;
    }
    return v;
}

// ---------------- Kernel 0: label cast (once, 8 KB output) ----------------
__global__ void k_labels(const long long* __restrict__ labels)
{
    int i = blockIdx.x * 256 + threadIdx.x;
    g_lab[i] = (unsigned char)labels[i];
}

// ---------------- Kernel 1: row-PAIR selection + fused loss ----------------
// Block b handles rows i_lo=b, i_hi=b+NB/2 (counter pair shares one threefry:
// o0 -> row lo, o1 -> row hi). Selection identical to R4/R7/R8 (threshold +
// exact top-8). Labels read from g_lab (8 KB per block, L2-resident).
// Tail: 18 dots on raw features; partner & anchor sum-of-squares computed
// inline with the same lane+32k summation pattern.
__global__ __launch_bounds__(256) void k_select_loss(
    const float* __restrict__ feat,
    uint32_t kp0, uint32_t kp1, uint32_t kn0, uint32_t kn1)
{
    const int i_lo = blockIdx.x;           // 0..4095
    const int i_hi = i_lo + (NB >> 1);
    const int tid = threadIdx.x, lane = tid & 31, wid = tid >> 5;

    __shared__ uint4 slab4[NB / 16];                      // labels, 8 KB
    __shared__ unsigned long long nsurv[2][NCAP];         // 8 KB
    __shared__ int ncnt[2];
    __shared__ short clist[2][CLS];                       // 1.25 KB
    __shared__ int ccnt[2];
    __shared__ unsigned long long spos[2][8];
    __shared__ int    sidx[2][1 + NNEG];                  // partner indices
    __shared__ float4 srow4[2][ND / 4];                   // anchor rows (4 KB)
    __shared__ float  sdots[2][1 + NNEG];                 // raw dots
    __shared__ float  ssqp[2][1 + NNEG];                  // partner sum-of-squares
    __shared__ float  sanc[2];                            // anchor sum-of-squares

    const unsigned char* slab = (const unsigned char*)slab4;

    for (int c = tid; c < NB / 16; c += 256)
        slab4[c] = ((const uint4*)g_lab)[c];
    if (tid < 2) { ncnt[tid] = 0; ccnt[tid] = 0; }
    __syncthreads();

    const unsigned int lab_lo = slab[i_lo];
    const unsigned int lab_hi = slab[i_hi];
    const uint32_t lablo4 = lab_lo * 0x01010101u;
    const uint32_t labhi4 = lab_hi * 0x01010101u;
    const uint32_t nbase = (uint32_t)i_lo * (uint32_t)NB;

    // ---- hot loop: 8192 threefry blocks, threshold filter ----
    for (int jb = tid * 4; jb < NB; jb += 1024) {
        uint32_t lw = ((const uint32_t*)slab)[jb >> 2];
        uint32_t eqlo = __vcmpeq4(lw, lablo4);            // 0xFF per match byte
        uint32_t eqhi = __vcmpeq4(lw, labhi4);
        #pragma unroll
        for (int q = 0; q < 4; q++) {
            int j = jb + q;
            uint32_t n = nbase + (uint32_t)j;
            uint32_t o0, o1;
            threefry2x32(kn0, kn1, n, n + HALFC, &o0, &o1);

            if (eqlo & (0xFFu << (8 * q))) {
                int p = atomicAdd(&ccnt[0], 1);
                if (p < CLS) clist[0][p] = (short)j;
            } else if (o0 >= THRESH_RAW) {
                int p = atomicAdd(&ncnt[0], 1);
                if (p < NCAP) nsurv[0][p] = pack_key(o0, j);
            }
            if (eqhi & (0xFFu << (8 * q))) {
                int p = atomicAdd(&ccnt[1], 1);
                if (p < CLS) clist[1][p] = (short)j;
            } else if (o1 >= THRESH_RAW) {
                int p = atomicAdd(&ncnt[1], 1);
                if (p < NCAP) nsurv[1][p] = pack_key(o1, j);
            }
        }
    }
    __syncthreads();

    // ---- sparse positive loops (kp key) ----
    unsigned long long bp_lo = 0ull, bp_hi = 0ull;
    {
        int c0 = min(ccnt[0], CLS);
        for (int t = tid; t < c0; t += 256) {
            int j = clist[0][t];
            if (j != i_lo) {
                uint32_t n = nbase + (uint32_t)j, o0, o1;
                threefry2x32(kp0, kp1, n, n + HALFC, &o0, &o1);
                unsigned long long p = pack_key(o0, j);
                if (p > bp_lo) bp_lo = p;
            }
        }
        int c1 = min(ccnt[1], CLS);
        for (int t = tid; t < c1; t += 256) {
            int j = clist[1][t];
            if (j != i_hi) {
                uint32_t n = nbase + (uint32_t)j, o0, o1;
                threefry2x32(kp0, kp1, n, n + HALFC, &o0, &o1);
                unsigned long long p = pack_key(o1, j);
                if (p > bp_hi) bp_hi = p;
            }
        }
    }
    bp_lo = warp_max_u64(bp_lo);
    bp_hi = warp_max_u64(bp_hi);
    if (lane == 0) { spos[0][wid] = bp_lo; spos[1][wid] = bp_hi; }
    __syncthreads();

    // ---- parallel tail: warps 0-1 extract top-8 + pos; warps 2-7 preload rows
    if (wid < 2) {
        const int row = wid;
        int cnt = min(ncnt[row], NCAP);
        unsigned long long v[NSLOT];
        #pragma unroll
        for (int s = 0; s < NSLOT; s++) {
            int idx = lane + 32 * s;
            v[s] = (idx < cnt) ? nsurv[row][idx] : 0ull;
        }
        #pragma unroll
        for (int r = 0; r < NNEG; r++) {
            unsigned long long loc = 0ull;
            #pragma unroll
            for (int s = 0; s < NSLOT; s++) if (v[s] > loc) loc = v[s];
            unsigned long long g = warp_max_u64(loc);
            #pragma unroll
            for (int s = 0; s < NSLOT; s++) if (v[s] == g) v[s] = 0ull;  // unique pop
            if (lane == 0) sidx[row][1 + r] = NB - 1 - (int)(g & 0x1FFFull);
        }
        unsigned long long bp = (lane < 8) ? spos[row][lane] : 0ull;
        bp = warp_max_u64(bp);
        if (lane == 0)
            sidx[row][0] = (bp == 0ull) ? 0 : (NB - 1 - (int)(bp & 0x1FFFull));
    } else {
        // load anchor rows i_lo, i_hi (raw) into smem: 256 float4 by 192 threads
        int idx = tid - 64;
        for (int c = idx; c < 2 * (ND / 4); c += 192) {
            int row = c >> 7;                 // 128 float4 per row
            int col = c & 127;
            const int i_row = row ? i_hi : i_lo;
            srow4[row][col] =
                ((const float4*)(feat + (size_t)i_row * ND))[col];
        }
    }
    __syncthreads();

    // ---- tasks: 0..17 = dots (+ partner ssq); 18,19 = anchor ssq ----
    for (int t = wid; t < 20; t += 8) {
        if (t < 18) {
            int row  = t / (1 + NNEG);
            int slot = t % (1 + NNEG);
            int j = sidx[row][slot];
            const float4* fr = (const float4*)(feat + (size_t)j * ND);
            const float4* ar = srow4[row];
            float acc = 0.0f, sq = 0.0f;
            #pragma unroll
            for (int k = 0; k < 4; k++) {
                float4 a = ar[lane + 32 * k];
                float4 b = fr[lane + 32 * k];
                acc += a.x * b.x + a.y * b.y + a.z * b.z + a.w * b.w;
                sq  += b.x * b.x + b.y * b.y + b.z * b.z + b.w * b.w;
            }
            #pragma unroll
            for (int o = 16; o; o >>= 1) {
                acc += __shfl_xor_sync(0xffffffffu, acc, o);
                sq  += __shfl_xor_sync(0xffffffffu, sq,  o);
            }
            if (lane == 0) { sdots[row][slot] = acc; ssqp[row][slot] = sq; }
        } else {
            int row = t - 18;
            const float4* ar = srow4[row];
            float sq = 0.0f;
            #pragma unroll
            for (int k = 0; k < 4; k++) {
                float4 a = ar[lane + 32 * k];
                sq += a.x * a.x + a.y * a.y + a.z * a.z + a.w * a.w;
            }
            #pragma unroll
            for (int o = 16; o; o >>= 1) sq += __shfl_xor_sync(0xffffffffu, sq, o);
            if (lane == 0) sanc[row] = sq;
        }
    }
    __syncthreads();

    // ---- loss epilogue: thread 0 -> row lo, thread 1 -> row hi ----
    if (tid < 2) {
        const int row = tid;
        const int i_row = row ? i_hi : i_lo;
        float inv_i = 1.0f / fmaxf(sqrtf(sanc[row]), 1e-12f);
        float sims[1 + NNEG];
        #pragma unroll
        for (int q = 0; q < 1 + NNEG; q++) {
            float inv_j = 1.0f / fmaxf(sqrtf(ssqp[row][q]), 1e-12f);
            sims[q] = sdots[row][q] * inv_i * inv_j;
        }
        float pos = sims[0] * 2.0f;          // / TEMPERATURE (0.5)
        float s[NNEG];
        #pragma unroll
        for (int q = 0; q < NNEG; q++) s[q] = sims[1 + q];
        float hard[3];
        #pragma unroll
        for (int r = 0; r < 3; r++) {        // stable top-3 (lower index wins)
            int bi = 0; float bv = s[0];
            #pragma unroll
            for (int q = 1; q < NNEG; q++) if (s[q] > bv) { bv = s[q]; bi = q; }
            hard[r] = bv * 2.0f;
            s[bi] = -3.0e38f;
        }
        float mx = fmaxf(fmaxf(pos, hard[0]), fmaxf(hard[1], hard[2]));
        float sum = expf(pos - mx) + expf(hard[0] - mx) +
                    expf(hard[1] - mx) + expf(hard[2] - mx);
        g_loss[i_row] = mx + logf(sum) - pos;
    }
}

// ---------------- Kernel 2: mean reduce ----------------
__global__ void k_reduce(float* __restrict__ out)
{
    __shared__ float s[256];
    int tid = threadIdx.x;
    float a = 0.0f;
    for (int i = tid; i < NB; i += 256) a += g_loss[i];
    s[tid] = a;
    __syncthreads();
    for (int off = 128; off; off >>= 1) {
        if (tid < off) s[tid] += s[tid + off];
        __syncthreads();
    }
    if (tid == 0) out[0] = s[0] / (float)NB;
}

// ---------------- Launch ----------------
extern "C" void kernel_launch(void* const* d_in, const int* in_sizes, int n_in,
                              void* d_out, int out_size)
{
    const float*     feat   = (const float*)d_in[0];
    const long long* labels = (const long long*)d_in[1];

    // seed 42 -> raw key (0, 42); original split: counts iota(4) -> pairs
    // (0,2),(1,3); kp=(a0,a1), kn=(b0,b1)
    uint32_t a0, b0, a1, b1;
    threefry2x32(0u, 42u, 0u, 2u, &a0, &b0);
    threefry2x32(0u, 42u, 1u, 3u, &a1, &b1);
    uint32_t kp0 = a0, kp1 = a1, kn0 = b0, kn1 = b1;

    k_labels     <<<NB / 256, 256>>>(labels);
    k_select_loss<<<NB / 2, 256>>>(feat, kp0, kp1, kn0, kn1);
    k_reduce     <<<1, 256>>>((float*)d_out);
}

// round 11
// speedup vs baseline: 1.1027x; 1.0652x over previous
#include <cuda_runtime.h>
#include <stdint.h>

// Fixed problem shape: features [8192, 512], labels [8192] in [0,64)
#define NB 8192
#define ND 512
#define NNEG 8
#define NLAB 64
#define HALFC 33554432u        // (8192*8192)/2
#define THRESH_RAW 0xFC000000u // raw-bits threshold == (2^23 * (1-1/64)) << 9
#define NCAP 512               // survivor cap/row (mean 128 incl same-label; 34 sigma)
#define NSLOT (NCAP / 32)
#define CLS 320                // class-list cap (mean 128; 17 sigma)

// Scratch (no cudaMalloc allowed)
__device__ unsigned char      g_lab[NB];
__device__ int                g_ccnt[NLAB];
__device__ short              g_cls[NLAB][CLS];
__device__ unsigned long long g_accum;   // fixed-point loss sum (det., order-free)

// ---------------- rotate ----------------
__host__ __device__ __forceinline__ uint32_t rotl32(uint32_t v, int r)
{
#ifdef __CUDA_ARCH__
    return __funnelshift_l(v, v, r);
#else
    return (v << r) | (v >> (32 - r));
#endif
}

// ---------------- Threefry-2x32 (20 rounds), original JAX convention ----------
__host__ __device__ __forceinline__ void threefry2x32(
    uint32_t k0, uint32_t k1, uint32_t x0, uint32_t x1,
    uint32_t* o0, uint32_t* o1)
{
    uint32_t ks2 = k0 ^ k1 ^ 0x1BD11BDAu;
    x0 += k0; x1 += k1;
#define TF_RND(r) { x0 += x1; x1 = rotl32(x1, r); x1 ^= x0; }
    TF_RND(13) TF_RND(15) TF_RND(26) TF_RND(6)  x0 += k1;  x1 += ks2 + 1u;
    TF_RND(17) TF_RND(29) TF_RND(16) TF_RND(24) x0 += ks2; x1 += k0  + 2u;
    TF_RND(13) TF_RND(15) TF_RND(26) TF_RND(6)  x0 += k0;  x1 += k1  + 3u;
    TF_RND(17) TF_RND(29) TF_RND(16) TF_RND(24) x0 += k1;  x1 += ks2 + 4u;
    TF_RND(13) TF_RND(15) TF_RND(26) TF_RND(6)  x0 += ks2; x1 += k0  + 5u;
#undef TF_RND
    *o0 = x0; *o1 = x1;
}

// ordering of gumbel == ordering of (bits>>9); tie -> lower j wins.
__device__ __forceinline__ unsigned long long pack_key(uint32_t bits, int j)
{
    return ((unsigned long long)(bits >> 9) << 13) |
           (unsigned long long)(NB - 1 - j);
}

__device__ __forceinline__ unsigned long long warp_max_u64(unsigned long long v)
{
    #pragma unroll
    for (int o = 16; o; o >>= 1) {
        unsigned long long u = __shfl_xor_sync(0xffffffffu, v, o);
        if (u > v) v = u;
    }
    return v;
}

// ---------------- Kernel 0: prep — labels, global class lists, accum reset ----
__global__ __launch_bounds__(1024) void k_prep(const long long* __restrict__ labels)
{
    __shared__ int scnt[NLAB];
    int tid = threadIdx.x;
    if (tid < NLAB) scnt[tid] = 0;
    if (tid == 0) g_accum = 0ull;
    __syncthreads();

    for (int i = tid; i < NB; i += 1024) {
        int lab = (int)labels[i] & (NLAB - 1);
        g_lab[i] = (unsigned char)lab;
        int p = atomicAdd(&scnt[lab], 1);
        if (p < CLS) g_cls[lab][p] = (short)i;
    }
    __syncthreads();
    if (tid < NLAB) g_ccnt[tid] = scnt[tid];
}

// ---------------- Kernel 1: row-PAIR selection + fused loss ----------------
// Block b: rows i_lo=b, i_hi=b+NB/2 (counter pair shares one threefry block:
// o0 -> row lo, o1 -> row hi). HOT LOOP is threefry + threshold ONLY — no
// label logic. Same-label survivors are filtered at extraction (candidates
// carry j; true negative top-8 all pass the threshold, P(miss) ~ 1e-40).
// Positives use precomputed global class lists. Loss accumulated fixed-point.
__global__ __launch_bounds__(256) void k_select_loss(
    const float* __restrict__ feat,
    uint32_t kp0, uint32_t kp1, uint32_t kn0, uint32_t kn1)
{
    const int i_lo = blockIdx.x;           // 0..4095
    const int i_hi = i_lo + (NB >> 1);
    const int tid = threadIdx.x, lane = tid & 31, wid = tid >> 5;

    __shared__ unsigned long long nsurv[2][NCAP];         // 8 KB
    __shared__ int ncnt[2];
    __shared__ unsigned long long spos[2][8];
    __shared__ int    sidx[2][1 + NNEG];                  // partner indices
    __shared__ float4 srow4[2][ND / 4];                   // anchor rows (4 KB)
    __shared__ float  sdots[2][1 + NNEG];
    __shared__ float  ssqp[2][1 + NNEG];
    __shared__ float  sanc[2];

    if (tid < 2) ncnt[tid] = 0;
    __syncthreads();

    const uint32_t nbase = (uint32_t)i_lo * (uint32_t)NB;

    // ---- hot loop: 8192 threefry blocks, threshold filter only ----
    for (int jb = tid * 4; jb < NB; jb += 1024) {
        #pragma unroll
        for (int q = 0; q < 4; q++) {
            int j = jb + q;
            uint32_t n = nbase + (uint32_t)j;
            uint32_t o0, o1;
            threefry2x32(kn0, kn1, n, n + HALFC, &o0, &o1);
            bool s0 = (o0 >= THRESH_RAW);
            bool s1 = (o1 >= THRESH_RAW);
            if (s0 | s1) {
                if (s0) {
                    int p = atomicAdd(&ncnt[0], 1);
                    if (p < NCAP) nsurv[0][p] = pack_key(o0, j);
                }
                if (s1) {
                    int p = atomicAdd(&ncnt[1], 1);
                    if (p < NCAP) nsurv[1][p] = pack_key(o1, j);
                }
            }
        }
    }

    const unsigned int lab_lo = g_lab[i_lo];
    const unsigned int lab_hi = g_lab[i_hi];

    // ---- sparse positive loops from global class lists (kp key) ----
    unsigned long long bp_lo = 0ull, bp_hi = 0ull;
    {
        int c0 = min(g_ccnt[lab_lo], CLS);
        for (int t = tid; t < c0; t += 256) {
            int j = g_cls[lab_lo][t];
            if (j != i_lo) {
                uint32_t n = nbase + (uint32_t)j, o0, o1;
                threefry2x32(kp0, kp1, n, n + HALFC, &o0, &o1);
                unsigned long long p = pack_key(o0, j);
                if (p > bp_lo) bp_lo = p;
            }
        }
        int c1 = min(g_ccnt[lab_hi], CLS);
        for (int t = tid; t < c1; t += 256) {
            int j = g_cls[lab_hi][t];
            if (j != i_hi) {
                uint32_t n = nbase + (uint32_t)j, o0, o1;
                threefry2x32(kp0, kp1, n, n + HALFC, &o0, &o1);
                unsigned long long p = pack_key(o1, j);
                if (p > bp_hi) bp_hi = p;
            }
        }
    }
    bp_lo = warp_max_u64(bp_lo);
    bp_hi = warp_max_u64(bp_hi);
    if (lane == 0) { spos[0][wid] = bp_lo; spos[1][wid] = bp_hi; }
    __syncthreads();

    // ---- tail: warps 0-1 filter + extract top-8 + pos; warps 2-7 preload rows
    if (wid < 2) {
        const int row = wid;
        const unsigned int lab_row = row ? lab_hi : lab_lo;
        int cnt = min(ncnt[row], NCAP);

        unsigned long long v[NSLOT];
        #pragma unroll
        for (int s = 0; s < NSLOT; s++) {
            int idx = lane + 32 * s;
            unsigned long long key = 0ull;
            if (idx < cnt) {
                key = nsurv[row][idx];
                int j = NB - 1 - (int)(key & 0x1FFFull);
                if ((unsigned int)g_lab[j] == lab_row) key = 0ull;  // drop same-label
            }
            v[s] = key;
        }
        #pragma unroll
        for (int r = 0; r < NNEG; r++) {
            unsigned long long loc = 0ull;
            #pragma unroll
            for (int s = 0; s < NSLOT; s++) if (v[s] > loc) loc = v[s];
            unsigned long long g = warp_max_u64(loc);
            #pragma unroll
            for (int s = 0; s < NSLOT; s++) if (v[s] == g) v[s] = 0ull;  // unique pop
            if (lane == 0) sidx[row][1 + r] = NB - 1 - (int)(g & 0x1FFFull);
        }
        unsigned long long bp = (lane < 8) ? spos[row][lane] : 0ull;
        bp = warp_max_u64(bp);
        if (lane == 0)
            sidx[row][0] = (bp == 0ull) ? 0 : (NB - 1 - (int)(bp & 0x1FFFull));
    } else {
        // load anchor rows i_lo, i_hi into smem: 256 float4 by 192 threads
        int idx = tid - 64;
        for (int c = idx; c < 2 * (ND / 4); c += 192) {
            int row = c >> 7;                 // 128 float4 per row
            int col = c & 127;
            const int i_row = row ? i_hi : i_lo;
            srow4[row][col] =
                ((const float4*)(feat + (size_t)i_row * ND))[col];
        }
    }
    __syncthreads();

    // ---- tasks: 0..17 = dots (+ partner ssq); 18,19 = anchor ssq ----
    for (int t = wid; t < 20; t += 8) {
        if (t < 18) {
            int row  = t / (1 + NNEG);
            int slot = t % (1 + NNEG);
            int j = sidx[row][slot];
            const float4* fr = (const float4*)(feat + (size_t)j * ND);
            const float4* ar = srow4[row];
            float acc = 0.0f, sq = 0.0f;
            #pragma unroll
            for (int k = 0; k < 4; k++) {
                float4 a = ar[lane + 32 * k];
                float4 b = fr[lane + 32 * k];
                acc += a.x * b.x + a.y * b.y + a.z * b.z + a.w * b.w;
                sq  += b.x * b.x + b.y * b.y + b.z * b.z + b.w * b.w;
            }
            #pragma unroll
            for (int o = 16; o; o >>= 1) {
                acc += __shfl_xor_sync(0xffffffffu, acc, o);
                sq  += __shfl_xor_sync(0xffffffffu, sq,  o);
            }
            if (lane == 0) { sdots[row][slot] = acc; ssqp[row][slot] = sq; }
        } else {
            int row = t - 18;
            const float4* ar = srow4[row];
            float sq = 0.0f;
            #pragma unroll
            for (int k = 0; k < 4; k++) {
                float4 a = ar[lane + 32 * k];
                sq += a.x * a.x + a.y * a.y + a.z * a.z + a.w * a.w;
            }
            #pragma unroll
            for (int o = 16; o; o >>= 1) sq += __shfl_xor_sync(0xffffffffu, sq, o);
            if (lane == 0) sanc[row] = sq;
        }
    }
    __syncthreads();

    // ---- loss epilogue: thread 0 -> row lo, thread 1 -> row hi ----
    if (tid < 2) {
        const int row = tid;
        float inv_i = 1.0f / fmaxf(sqrtf(sanc[row]), 1e-12f);
        float sims[1 + NNEG];
        #pragma unroll
        for (int q = 0; q < 1 + NNEG; q++) {
            float inv_j = 1.0f / fmaxf(sqrtf(ssqp[row][q]), 1e-12f);
            sims[q] = sdots[row][q] * inv_i * inv_j;
        }
        float pos = sims[0] * 2.0f;          // / TEMPERATURE (0.5)
        float s[NNEG];
        #pragma unroll
        for (int q = 0; q < NNEG; q++) s[q] = sims[1 + q];
        float hard[3];
        #pragma unroll
        for (int r = 0; r < 3; r++) {        // stable top-3 (lower index wins)
            int bi = 0; float bv = s[0];
            #pragma unroll
            for (int q = 1; q < NNEG; q++) if (s[q] > bv) { bv = s[q]; bi = q; }
            hard[r] = bv * 2.0f;
            s[bi] = -3.0e38f;
        }
        float mx = fmaxf(fmaxf(pos, hard[0]), fmaxf(hard[1], hard[2]));
        float sum = expf(pos - mx) + expf(hard[0] - mx) +
                    expf(hard[1] - mx) + expf(hard[2] - mx);
        float loss = mx + logf(sum) - pos;   // >= 0 always
        // fixed-point accumulate: integer atomic sum is order-independent
        unsigned long long q64 = (unsigned long long)((double)loss * 4294967296.0);
        atomicAdd(&g_accum, q64);
    }
}

// ---------------- Kernel 2: finalize mean ----------------
__global__ void k_final(float* __restrict__ out)
{
    out[0] = (float)((double)g_accum * (1.0 / 4294967296.0) / (double)NB);
}

// ---------------- Launch ----------------
extern "C" void kernel_launch(void* const* d_in, const int* in_sizes, int n_in,
                              void* d_out, int out_size)
{
    const float*     feat   = (const float*)d_in[0];
    const long long* labels = (const long long*)d_in[1];

    // seed 42 -> raw key (0, 42); original split: counts iota(4) -> pairs
    // (0,2),(1,3); kp=(a0,a1), kn=(b0,b1)
    uint32_t a0, b0, a1, b1;
    threefry2x32(0u, 42u, 0u, 2u, &a0, &b0);
    threefry2x32(0u, 42u, 1u, 3u, &a1, &b1);
    uint32_t kp0 = a0, kp1 = a1, kn0 = b0, kn1 = b1;

    k_prep       <<<1, 1024>>>(labels);
    k_select_loss<<<NB / 2, 256>>>(feat, kp0, kp1, kn0, kn1);
    k_final      <<<1, 1>>>((float*)d_out);
}